// round 2
// baseline (speedup 1.0000x reference)
#include <cuda_runtime.h>
#include <math.h>

#define NB 32768
#define HD 512
#define DV 256
#define NP 512
#define RHO_MAXF 9.0f
#define DELTAF 0.001f
#define EPSF 1e-8f
#define PIF 3.14159265358979f

// ---------------- scratch (__device__ globals: no allocations allowed) ----------------
__device__ float g_H [NB*HD];
__device__ float g_Eh[NB*HD];
__device__ float g_Er[NB*HD];
__device__ float g_Et[NB*HD];
__device__ float g_Vh[NB*DV];
__device__ float g_Vt[NB*DV];
__device__ float g_TH[NB*NP];
__device__ float g_thT[NP*NB];
__device__ float g_uhT[DV*NB];
__device__ float g_utT[DV*NB];
__device__ float g_urT[DV*NB];
__device__ float g_reh[NB];
__device__ float g_rrr[NB];
__device__ float g_ret[NB];
__device__ float g_invh[NB];
__device__ float g_invt[NB];

__device__ __forceinline__ float softplusf(float x) {
    return (x > 20.f) ? x : log1pf(expf(x));
}

// ---------------- NT SGEMM: C[M,N] = A[M,K] * W[N,K]^T + bias (+relu | +residual) ----
// mode 0: +bias; mode 1: relu(+bias); mode 2: +bias + R
__global__ __launch_bounds__(256, 2)
void sgemm_nt(const float* __restrict__ A, const float* __restrict__ Wm,
              const float* __restrict__ bias, const float* __restrict__ R,
              float* __restrict__ C, int M, int N, int K, int mode)
{
    __shared__ __align__(16) float As[2][8][128];
    __shared__ __align__(16) float Bs[2][8][128];
    const int tid = threadIdx.x;
    const int m0 = blockIdx.y * 128;
    const int n0 = blockIdx.x * 128;
    const int lr = tid >> 1;
    const int lc = (tid & 1) * 4;
    const float* Ag = A + (size_t)(m0 + lr) * K + lc;
    const float* Bg = Wm + (size_t)(n0 + lr) * K + lc;
    const int msub = (tid >> 4) * 8;
    const int nsub = (tid & 15) * 8;

    float acc[8][8];
    #pragma unroll
    for (int i = 0; i < 8; i++)
        #pragma unroll
        for (int j = 0; j < 8; j++) acc[i][j] = 0.f;

    // prefetch tile 0
    float4 a4 = *(const float4*)Ag;
    float4 b4 = *(const float4*)Bg;
    As[0][lc+0][lr] = a4.x; As[0][lc+1][lr] = a4.y; As[0][lc+2][lr] = a4.z; As[0][lc+3][lr] = a4.w;
    Bs[0][lc+0][lr] = b4.x; Bs[0][lc+1][lr] = b4.y; Bs[0][lc+2][lr] = b4.z; Bs[0][lc+3][lr] = b4.w;
    __syncthreads();

    const int nt = K >> 3;
    int buf = 0;
    for (int t = 0; t < nt; ++t) {
        float4 na, nb;
        if (t + 1 < nt) {
            na = *(const float4*)(Ag + (t + 1) * 8);
            nb = *(const float4*)(Bg + (t + 1) * 8);
        }
        #pragma unroll
        for (int kk = 0; kk < 8; ++kk) {
            float af[8], bf[8];
            *(float4*)&af[0] = *(const float4*)&As[buf][kk][msub];
            *(float4*)&af[4] = *(const float4*)&As[buf][kk][msub + 4];
            *(float4*)&bf[0] = *(const float4*)&Bs[buf][kk][nsub];
            *(float4*)&bf[4] = *(const float4*)&Bs[buf][kk][nsub + 4];
            #pragma unroll
            for (int i = 0; i < 8; i++)
                #pragma unroll
                for (int j = 0; j < 8; j++)
                    acc[i][j] = fmaf(af[i], bf[j], acc[i][j]);
        }
        if (t + 1 < nt) {
            const int nbuf = buf ^ 1;
            As[nbuf][lc+0][lr] = na.x; As[nbuf][lc+1][lr] = na.y; As[nbuf][lc+2][lr] = na.z; As[nbuf][lc+3][lr] = na.w;
            Bs[nbuf][lc+0][lr] = nb.x; Bs[nbuf][lc+1][lr] = nb.y; Bs[nbuf][lc+2][lr] = nb.z; Bs[nbuf][lc+3][lr] = nb.w;
            __syncthreads();
            buf = nbuf;
        }
    }

    #pragma unroll
    for (int i = 0; i < 8; i++) {
        const int m = m0 + msub + i;
        #pragma unroll
        for (int j = 0; j < 8; j += 4) {
            const int n = n0 + nsub + j;
            float4 v;
            v.x = acc[i][j+0] + bias[n+0];
            v.y = acc[i][j+1] + bias[n+1];
            v.z = acc[i][j+2] + bias[n+2];
            v.w = acc[i][j+3] + bias[n+3];
            if (mode == 1) {
                v.x = fmaxf(v.x, 0.f); v.y = fmaxf(v.y, 0.f);
                v.z = fmaxf(v.z, 0.f); v.w = fmaxf(v.w, 0.f);
            } else if (mode == 2) {
                float4 r = *(const float4*)&R[(size_t)m * N + n];
                v.x += r.x; v.y += r.y; v.z += r.z; v.w += r.w;
            }
            *(float4*)&C[(size_t)m * N + n] = v;
        }
    }
}

// ---------------- three N=1 GEMVs fused: re_h, rr_r, re_t -----------------------------
__device__ __forceinline__ float dot4f(float4 a, float4 b) {
    return a.x*b.x + a.y*b.y + a.z*b.z + a.w*b.w;
}

__global__ void gemv3(const float* __restrict__ Eh, const float* __restrict__ Er,
                      const float* __restrict__ Et,
                      const float* __restrict__ Wre, const float* __restrict__ bre,
                      const float* __restrict__ Wrr, const float* __restrict__ brr,
                      float* __restrict__ reh, float* __restrict__ rrr, float* __restrict__ ret)
{
    const int warp = (blockIdx.x * blockDim.x + threadIdx.x) >> 5;
    const int lane = threadIdx.x & 31;
    if (warp >= NB) return;
    const float* eh = Eh + (size_t)warp * HD;
    const float* er = Er + (size_t)warp * HD;
    const float* et = Et + (size_t)warp * HD;
    float s1 = 0.f, s2 = 0.f, s3 = 0.f;
    #pragma unroll
    for (int k = lane * 4; k < HD; k += 128) {
        float4 wre4 = *(const float4*)&Wre[k];
        float4 wrr4 = *(const float4*)&Wrr[k];
        s1 += dot4f(*(const float4*)&eh[k], wre4);
        s2 += dot4f(*(const float4*)&er[k], wrr4);
        s3 += dot4f(*(const float4*)&et[k], wre4);
    }
    #pragma unroll
    for (int o = 16; o > 0; o >>= 1) {
        s1 += __shfl_down_sync(0xffffffffu, s1, o);
        s2 += __shfl_down_sync(0xffffffffu, s2, o);
        s3 += __shfl_down_sync(0xffffffffu, s3, o);
    }
    if (lane == 0) {
        reh[warp] = s1 + bre[0];
        rrr[warp] = s2 + brr[0];
        ret[warp] = s3 + bre[0];
    }
}

// ---------------- row inverse-norm (warp per row) -------------------------------------
__global__ void rownorm(const float* __restrict__ V, float* __restrict__ inv, int W)
{
    const int warp = (blockIdx.x * blockDim.x + threadIdx.x) >> 5;
    const int lane = threadIdx.x & 31;
    if (warp >= NB) return;
    const float* v = V + (size_t)warp * W;
    float s = 0.f;
    for (int k = lane * 4; k < W; k += 128) {
        float4 a = *(const float4*)&v[k];
        s += a.x*a.x + a.y*a.y + a.z*a.z + a.w*a.w;
    }
    #pragma unroll
    for (int o = 16; o > 0; o >>= 1) s += __shfl_down_sync(0xffffffffu, s, o);
    if (lane == 0) inv[warp] = 1.f / (sqrtf(s) + EPSF);
}

// ---------------- transpose (+ optional pi*tanh or per-row scale) ---------------------
// mode 0: out[c, b] = pi * tanhf(in[b, c]);  mode 1: out[c, b] = in[b, c] * inv[b]
__global__ void transpose_op(const float* __restrict__ in, float* __restrict__ out,
                             const float* __restrict__ inv, int N, int mode)
{
    __shared__ float tile[32][33];
    const int tx = threadIdx.x, ty = threadIdx.y;
    const int x = blockIdx.x * 32 + tx;    // col in input
    const int y0 = blockIdx.y * 32;        // row block (b)
    #pragma unroll
    for (int j = ty; j < 32; j += 8)
        tile[j][tx] = in[(size_t)(y0 + j) * N + x];
    __syncthreads();
    const int b = y0 + tx;
    const int c0 = blockIdx.x * 32;
    float scale = (mode == 1) ? inv[b] : 1.f;
    #pragma unroll
    for (int j = ty; j < 32; j += 8) {
        float v = tile[tx][j];
        if (mode == 0) v = PIF * tanhf(v);
        else v *= scale;
        out[(size_t)(c0 + j) * NB + b] = v;
    }
}

// ---------------- fused rotation + slerp + score --------------------------------------
__global__ void rot_score(
    const float* __restrict__ uhT, const float* __restrict__ utT,
    const float* __restrict__ thT, float* __restrict__ urT,
    const float* __restrict__ sim,
    const float* __restrict__ reh, const float* __restrict__ rrr, const float* __restrict__ ret,
    const float* __restrict__ ga_rho, const float* __restrict__ gb_rho,
    const float* __restrict__ ga_phi, const float* __restrict__ gb_phi,
    float* __restrict__ out)
{
    const int b = blockIdx.x * blockDim.x + threadIdx.x;
    if (b >= NB) return;

    // ---- pass 1: rotations t = 0..255 (i = t, j = (t+1)%256), streaming with carry ---
    float cur = uhT[b];
    float u0w = 0.f;
    #pragma unroll 4
    for (int i = 0; i < 255; i++) {
        float s, c; sincosf(thT[(size_t)i * NB + b], &s, &c);
        float nxt = uhT[(size_t)(i + 1) * NB + b];
        float wi = c * cur - s * nxt;
        urT[(size_t)i * NB + b] = wi;
        if (i == 0) u0w = wi;
        cur = s * cur + c * nxt;
    }
    {
        float s, c; sincosf(thT[(size_t)255 * NB + b], &s, &c);
        float w255 = c * cur - s * u0w;   // rotates (255, 0), j=0 already updated this pass
        float w0   = s * cur + c * u0w;
        urT[(size_t)255 * NB + b] = w255;
        urT[b] = w0;
    }

    // ---- pass 2: t = 256..511, fused with dot-product accumulation -------------------
    float dhr = 0.f, dht = 0.f, drt = 0.f, ssq = 0.f;
    const float uh0 = uhT[b], ut0 = utT[b];
    cur = urT[b];
    float w0sav = 0.f;
    #pragma unroll 4
    for (int i = 0; i < 255; i++) {
        float s, c; sincosf(thT[(size_t)(256 + i) * NB + b], &s, &c);
        float nxt = urT[(size_t)(i + 1) * NB + b];
        float wi = c * cur - s * nxt;
        cur = s * cur + c * nxt;
        if (i == 0) {
            w0sav = wi;               // element 0 gets touched again at the wrap
        } else {
            float uh = uhT[(size_t)i * NB + b];
            float ut = utT[(size_t)i * NB + b];
            ssq += wi * wi; dhr += wi * uh; drt += wi * ut; dht += uh * ut;
        }
    }
    float w255f, w0f;
    {
        float s, c; sincosf(thT[(size_t)511 * NB + b], &s, &c);
        w255f = c * cur - s * w0sav;
        w0f   = s * cur + c * w0sav;
    }
    {
        float uh255 = uhT[(size_t)255 * NB + b], ut255 = utT[(size_t)255 * NB + b];
        ssq += w255f * w255f + w0f * w0f;
        dhr += w255f * uh255 + w0f * uh0;
        drt += w255f * ut255 + w0f * ut0;
        dht += uh255 * ut255 + uh0 * ut0;
    }

    // ---- scalar epilogue: slerp via dot algebra + hyperbolic score -------------------
    float nr = sqrtf(ssq);
    float inv_rot = 1.f / (nr + EPSF);
    float dhr_n = dhr * inv_rot;                       // dot(u_h, u_rot)
    float dotc = fminf(fmaxf(dhr_n, -1.f + EPSF), 1.f - EPSF);
    float omega = acosf(dotc);
    float sin_om = sinf(omega);
    float sv = sim[b];
    float grho = 1.f / (1.f + expf(-(ga_rho[0] * sv + gb_rho[0])));
    float gphi = 1.f / (1.f + expf(-(ga_phi[0] * sv + gb_phi[0])));
    float ca, cb;
    if (omega > DELTAF) {
        float iso = 1.f / (sin_om + EPSF);
        ca = sinf((1.f - gphi) * omega) * iso;
        cb = sinf(gphi * omega) * iso;
    } else {
        ca = 1.f - gphi; cb = gphi;
    }
    // u_prime = l2norm(ca*u_h + cb*u_rot): derive dot(u_prime, u_t) without vectors
    float nrn = nr * inv_rot;                          // ||u_rot|| after l2norm
    float np2 = ca * ca + cb * cb * nrn * nrn + 2.f * ca * cb * dhr_n;
    float npv = sqrtf(fmaxf(np2, 0.f));
    float inv_np = 1.f / (npv + EPSF);
    float dpt = (ca * dht + cb * drt * inv_rot) * inv_np;

    float rho_h = fminf(softplusf(reh[b]), RHO_MAXF);
    float rho_p = fminf(fmaxf(rho_h + rrr[b] * grho, 0.f), RHO_MAXF);
    float rho_t = fminf(softplusf(ret[b]), RHO_MAXF);
    out[b] = -coshf(rho_p) * coshf(rho_t) + sinhf(rho_p) * sinhf(rho_t) * dpt;
}

// ---------------- launch --------------------------------------------------------------
extern "C" void kernel_launch(void* const* d_in, const int* in_sizes, int n_in,
                              void* d_out, int out_size)
{
    const float* ent  = (const float*)d_in[0];
    const float* rel  = (const float*)d_in[1];
    const float* lab  = (const float*)d_in[2];
    const float* sim  = (const float*)d_in[3];
    const float* Wv   = (const float*)d_in[4];
    const float* bv   = (const float*)d_in[5];
    const float* Wre  = (const float*)d_in[6];
    const float* bre  = (const float*)d_in[7];
    const float* Wrr  = (const float*)d_in[8];
    const float* brr  = (const float*)d_in[9];
    const float* Wt   = (const float*)d_in[10];
    const float* bt   = (const float*)d_in[11];
    const float* ga_rho = (const float*)d_in[12];
    const float* gb_rho = (const float*)d_in[13];
    const float* ga_phi = (const float*)d_in[14];
    const float* gb_phi = (const float*)d_in[15];
    const float* W1   = (const float*)d_in[16];
    const float* b1   = (const float*)d_in[17];
    const float* W2   = (const float*)d_in[18];
    const float* b2   = (const float*)d_in[19];
    float* out = (float*)d_out;

    float *H, *Eh, *Er, *Et, *Vh, *Vt, *TH, *thT, *uhT, *utT, *urT;
    float *reh, *rrr, *ret, *invh, *invt;
    cudaGetSymbolAddress((void**)&H,   g_H);
    cudaGetSymbolAddress((void**)&Eh,  g_Eh);
    cudaGetSymbolAddress((void**)&Er,  g_Er);
    cudaGetSymbolAddress((void**)&Et,  g_Et);
    cudaGetSymbolAddress((void**)&Vh,  g_Vh);
    cudaGetSymbolAddress((void**)&Vt,  g_Vt);
    cudaGetSymbolAddress((void**)&TH,  g_TH);
    cudaGetSymbolAddress((void**)&thT, g_thT);
    cudaGetSymbolAddress((void**)&uhT, g_uhT);
    cudaGetSymbolAddress((void**)&utT, g_utT);
    cudaGetSymbolAddress((void**)&urT, g_urT);
    cudaGetSymbolAddress((void**)&reh, g_reh);
    cudaGetSymbolAddress((void**)&rrr, g_rrr);
    cudaGetSymbolAddress((void**)&ret, g_ret);
    cudaGetSymbolAddress((void**)&invh, g_invh);
    cudaGetSymbolAddress((void**)&invt, g_invt);

    dim3 g4(4, NB / 128), g2(2, NB / 128), blk(256);

    // pre(x) = x + relu(x@W1^T + b1)@W2^T + b2 for the three embeddings
    sgemm_nt<<<g4, blk>>>(ent, W1, b1, nullptr, H,  NB, HD, HD, 1);
    sgemm_nt<<<g4, blk>>>(H,   W2, b2, ent,     Eh, NB, HD, HD, 2);
    sgemm_nt<<<g4, blk>>>(rel, W1, b1, nullptr, H,  NB, HD, HD, 1);
    sgemm_nt<<<g4, blk>>>(H,   W2, b2, rel,     Er, NB, HD, HD, 2);
    sgemm_nt<<<g4, blk>>>(lab, W1, b1, nullptr, H,  NB, HD, HD, 1);
    sgemm_nt<<<g4, blk>>>(H,   W2, b2, lab,     Et, NB, HD, HD, 2);

    // polar projections + theta logits
    sgemm_nt<<<g2, blk>>>(Eh, Wv, bv, nullptr, Vh, NB, DV, HD, 0);
    sgemm_nt<<<g2, blk>>>(Et, Wv, bv, nullptr, Vt, NB, DV, HD, 0);
    sgemm_nt<<<g4, blk>>>(Er, Wt, bt, nullptr, TH, NB, NP, HD, 0);

    // scalar GEMVs (rho logits / delta_rho)
    gemv3<<<NB / 8, 256>>>(Eh, Er, Et, Wre, bre, Wrr, brr, reh, rrr, ret);

    // row norms + normalized transposes for coalesced rotation access
    rownorm<<<NB / 8, 256>>>(Vh, invh, DV);
    rownorm<<<NB / 8, 256>>>(Vt, invt, DV);
    transpose_op<<<dim3(NP / 32, NB / 32), dim3(32, 8)>>>(TH, thT, nullptr, NP, 0);
    transpose_op<<<dim3(DV / 32, NB / 32), dim3(32, 8)>>>(Vh, uhT, invh, DV, 1);
    transpose_op<<<dim3(DV / 32, NB / 32), dim3(32, 8)>>>(Vt, utT, invt, DV, 1);

    // fused Givens sweeps + slerp + hyperbolic score
    rot_score<<<NB / 256, 256>>>(uhT, utT, thT, urT, sim, reh, rrr, ret,
                                 ga_rho, gb_rho, ga_phi, gb_phi, out);
    (void)in_sizes; (void)n_in; (void)out_size;
}

// round 3
// speedup vs baseline: 3.8575x; 3.8575x over previous
#include <cuda_runtime.h>
#include <math.h>
#include <stdint.h>

#define NB 32768
#define HD 512
#define DV 256
#define NP 512
#define RHO_MAXF 9.0f
#define DELTAF 0.001f
#define EPSF 1e-8f
#define PIF 3.14159265358979f

// ---------------- scratch (__device__ globals: no allocations allowed) ----------------
__device__ float g_H [NB*HD];
__device__ float g_Eh[NB*HD];
__device__ float g_Er[NB*HD];
__device__ float g_Et[NB*HD];
__device__ float g_Vh[NB*DV];
__device__ float g_Vt[NB*DV];
__device__ float g_TH[NB*NP];
__device__ float g_thT[NP*NB];
__device__ float g_uhT[DV*NB];
__device__ float g_utT[DV*NB];
__device__ float g_urT[DV*NB];
__device__ float g_reh[NB];
__device__ float g_rrr[NB];
__device__ float g_ret[NB];
__device__ float g_invh[NB];
__device__ float g_invt[NB];

__device__ __forceinline__ float softplusf(float x) {
    return (x > 20.f) ? x : log1pf(expf(x));
}

__device__ __forceinline__ uint32_t f2tf32(float x) {
    uint32_t r;
    asm("cvt.rna.tf32.f32 %0, %1;" : "=r"(r) : "f"(x));
    return r;
}

// ---------------- TF32 tensor-core NT GEMM ------------------------------------------
// C[M,N] = A[M,K] * W[N,K]^T + bias (+relu | +residual)
// Block 128x128, 8 warps (4m x 2n), warp tile 32x64, KTILE=16 (2 k-steps of 8).
// Smem row stride = 20 words (16 + 4 pad) -> conflict-free fragment reads.
#define SMS 20

__global__ __launch_bounds__(256)
void sgemm_tf32(const float* __restrict__ A, const float* __restrict__ Wm,
                const float* __restrict__ bias, const float* __restrict__ R,
                float* __restrict__ C, int M, int N, int K, int mode)
{
    __shared__ uint32_t As[2][128 * SMS];
    __shared__ uint32_t Bs[2][128 * SMS];

    const int tid  = threadIdx.x;
    const int wid  = tid >> 5;
    const int lane = tid & 31;
    const int g    = lane >> 2;     // group id 0..7
    const int tg   = lane & 3;      // thread-in-group 0..3
    const int m0   = blockIdx.y * 128;
    const int n0   = blockIdx.x * 128;
    const int moff = (wid & 3) * 32;
    const int noff = (wid >> 2) * 64;

    // global load mapping: 2 float4 per thread per tile per matrix
    // idx = tid + 256*p ; row = idx>>2 (0..127) ; col4 = (idx&3)*4
    const int r0l = tid >> 2;
    const int c0l = (tid & 3) * 4;

    const float* Ag = A  + (size_t)(m0) * K;
    const float* Bg = Wm + (size_t)(n0) * K;

    float acc[2][8][4];
    #pragma unroll
    for (int mt = 0; mt < 2; mt++)
        #pragma unroll
        for (int nt = 0; nt < 8; nt++)
            #pragma unroll
            for (int q = 0; q < 4; q++) acc[mt][nt][q] = 0.f;

    // ---- load tile 0 ----
    {
        #pragma unroll
        for (int p = 0; p < 2; p++) {
            const int row = r0l + p * 64;
            float4 a4 = *(const float4*)&Ag[(size_t)row * K + c0l];
            float4 b4 = *(const float4*)&Bg[(size_t)row * K + c0l];
            uint32_t* as = &As[0][row * SMS + c0l];
            uint32_t* bs = &Bs[0][row * SMS + c0l];
            as[0] = f2tf32(a4.x); as[1] = f2tf32(a4.y); as[2] = f2tf32(a4.z); as[3] = f2tf32(a4.w);
            bs[0] = f2tf32(b4.x); bs[1] = f2tf32(b4.y); bs[2] = f2tf32(b4.z); bs[3] = f2tf32(b4.w);
        }
    }
    __syncthreads();

    const int kt = K >> 4;   // number of 16-wide K tiles
    int buf = 0;
    for (int t = 0; t < kt; ++t) {
        float4 na[2], nb[2];
        if (t + 1 < kt) {
            const int k0 = (t + 1) * 16;
            #pragma unroll
            for (int p = 0; p < 2; p++) {
                const int row = r0l + p * 64;
                na[p] = *(const float4*)&Ag[(size_t)row * K + k0 + c0l];
                nb[p] = *(const float4*)&Bg[(size_t)row * K + k0 + c0l];
            }
        }

        #pragma unroll
        for (int ks = 0; ks < 2; ++ks) {
            const int kb = ks * 8;
            uint32_t af[2][4], bf[8][2];
            #pragma unroll
            for (int mt = 0; mt < 2; mt++) {
                const int r = moff + mt * 16 + g;
                af[mt][0] = As[buf][r * SMS + kb + tg];
                af[mt][1] = As[buf][(r + 8) * SMS + kb + tg];
                af[mt][2] = As[buf][r * SMS + kb + tg + 4];
                af[mt][3] = As[buf][(r + 8) * SMS + kb + tg + 4];
            }
            #pragma unroll
            for (int nt = 0; nt < 8; nt++) {
                const int nr = noff + nt * 8 + g;
                bf[nt][0] = Bs[buf][nr * SMS + kb + tg];
                bf[nt][1] = Bs[buf][nr * SMS + kb + tg + 4];
            }
            #pragma unroll
            for (int mt = 0; mt < 2; mt++)
                #pragma unroll
                for (int nt = 0; nt < 8; nt++) {
                    asm volatile(
                        "mma.sync.aligned.m16n8k8.row.col.f32.tf32.tf32.f32 "
                        "{%0,%1,%2,%3}, {%4,%5,%6,%7}, {%8,%9}, {%0,%1,%2,%3};"
                        : "+f"(acc[mt][nt][0]), "+f"(acc[mt][nt][1]),
                          "+f"(acc[mt][nt][2]), "+f"(acc[mt][nt][3])
                        : "r"(af[mt][0]), "r"(af[mt][1]), "r"(af[mt][2]), "r"(af[mt][3]),
                          "r"(bf[nt][0]), "r"(bf[nt][1]));
                }
        }

        if (t + 1 < kt) {
            const int nbuf = buf ^ 1;
            #pragma unroll
            for (int p = 0; p < 2; p++) {
                const int row = r0l + p * 64;
                uint32_t* as = &As[nbuf][row * SMS + c0l];
                uint32_t* bs = &Bs[nbuf][row * SMS + c0l];
                as[0] = f2tf32(na[p].x); as[1] = f2tf32(na[p].y); as[2] = f2tf32(na[p].z); as[3] = f2tf32(na[p].w);
                bs[0] = f2tf32(nb[p].x); bs[1] = f2tf32(nb[p].y); bs[2] = f2tf32(nb[p].z); bs[3] = f2tf32(nb[p].w);
            }
            __syncthreads();
            buf = nbuf;
        }
    }

    // ---- epilogue ----
    #pragma unroll
    for (int mt = 0; mt < 2; mt++) {
        #pragma unroll
        for (int nt = 0; nt < 8; nt++) {
            const int n = n0 + noff + nt * 8 + 2 * tg;
            const int ra = m0 + moff + mt * 16 + g;
            const int rb = ra + 8;
            float bx = bias[n], by = bias[n + 1];
            float2 v0 = make_float2(acc[mt][nt][0] + bx, acc[mt][nt][1] + by);
            float2 v1 = make_float2(acc[mt][nt][2] + bx, acc[mt][nt][3] + by);
            if (mode == 1) {
                v0.x = fmaxf(v0.x, 0.f); v0.y = fmaxf(v0.y, 0.f);
                v1.x = fmaxf(v1.x, 0.f); v1.y = fmaxf(v1.y, 0.f);
            } else if (mode == 2) {
                float2 r0v = *(const float2*)&R[(size_t)ra * N + n];
                float2 r1v = *(const float2*)&R[(size_t)rb * N + n];
                v0.x += r0v.x; v0.y += r0v.y;
                v1.x += r1v.x; v1.y += r1v.y;
            }
            *(float2*)&C[(size_t)ra * N + n] = v0;
            *(float2*)&C[(size_t)rb * N + n] = v1;
        }
    }
}

// ---------------- three N=1 GEMVs fused: re_h, rr_r, re_t -----------------------------
__device__ __forceinline__ float dot4f(float4 a, float4 b) {
    return a.x*b.x + a.y*b.y + a.z*b.z + a.w*b.w;
}

__global__ void gemv3(const float* __restrict__ Eh, const float* __restrict__ Er,
                      const float* __restrict__ Et,
                      const float* __restrict__ Wre, const float* __restrict__ bre,
                      const float* __restrict__ Wrr, const float* __restrict__ brr,
                      float* __restrict__ reh, float* __restrict__ rrr, float* __restrict__ ret)
{
    const int warp = (blockIdx.x * blockDim.x + threadIdx.x) >> 5;
    const int lane = threadIdx.x & 31;
    if (warp >= NB) return;
    const float* eh = Eh + (size_t)warp * HD;
    const float* er = Er + (size_t)warp * HD;
    const float* et = Et + (size_t)warp * HD;
    float s1 = 0.f, s2 = 0.f, s3 = 0.f;
    #pragma unroll
    for (int k = lane * 4; k < HD; k += 128) {
        float4 wre4 = *(const float4*)&Wre[k];
        float4 wrr4 = *(const float4*)&Wrr[k];
        s1 += dot4f(*(const float4*)&eh[k], wre4);
        s2 += dot4f(*(const float4*)&er[k], wrr4);
        s3 += dot4f(*(const float4*)&et[k], wre4);
    }
    #pragma unroll
    for (int o = 16; o > 0; o >>= 1) {
        s1 += __shfl_down_sync(0xffffffffu, s1, o);
        s2 += __shfl_down_sync(0xffffffffu, s2, o);
        s3 += __shfl_down_sync(0xffffffffu, s3, o);
    }
    if (lane == 0) {
        reh[warp] = s1 + bre[0];
        rrr[warp] = s2 + brr[0];
        ret[warp] = s3 + bre[0];
    }
}

// ---------------- row inverse-norm (warp per row) -------------------------------------
__global__ void rownorm(const float* __restrict__ V, float* __restrict__ inv, int W)
{
    const int warp = (blockIdx.x * blockDim.x + threadIdx.x) >> 5;
    const int lane = threadIdx.x & 31;
    if (warp >= NB) return;
    const float* v = V + (size_t)warp * W;
    float s = 0.f;
    for (int k = lane * 4; k < W; k += 128) {
        float4 a = *(const float4*)&v[k];
        s += a.x*a.x + a.y*a.y + a.z*a.z + a.w*a.w;
    }
    #pragma unroll
    for (int o = 16; o > 0; o >>= 1) s += __shfl_down_sync(0xffffffffu, s, o);
    if (lane == 0) inv[warp] = 1.f / (sqrtf(s) + EPSF);
}

// ---------------- transpose (+ optional pi*tanh or per-row scale) ---------------------
// mode 0: out[c, b] = pi * tanhf(in[b, c]);  mode 1: out[c, b] = in[b, c] * inv[b]
__global__ void transpose_op(const float* __restrict__ in, float* __restrict__ out,
                             const float* __restrict__ inv, int N, int mode)
{
    __shared__ float tile[32][33];
    const int tx = threadIdx.x, ty = threadIdx.y;
    const int x = blockIdx.x * 32 + tx;
    const int y0 = blockIdx.y * 32;
    #pragma unroll
    for (int j = ty; j < 32; j += 8)
        tile[j][tx] = in[(size_t)(y0 + j) * N + x];
    __syncthreads();
    const int b = y0 + tx;
    const int c0 = blockIdx.x * 32;
    float scale = (mode == 1) ? inv[b] : 1.f;
    #pragma unroll
    for (int j = ty; j < 32; j += 8) {
        float v = tile[tx][j];
        if (mode == 0) v = PIF * tanhf(v);
        else v *= scale;
        out[(size_t)(c0 + j) * NB + b] = v;
    }
}

// ---------------- fused rotation + slerp + score --------------------------------------
__global__ void rot_score(
    const float* __restrict__ uhT, const float* __restrict__ utT,
    const float* __restrict__ thT, float* __restrict__ urT,
    const float* __restrict__ sim,
    const float* __restrict__ reh, const float* __restrict__ rrr, const float* __restrict__ ret,
    const float* __restrict__ ga_rho, const float* __restrict__ gb_rho,
    const float* __restrict__ ga_phi, const float* __restrict__ gb_phi,
    float* __restrict__ out)
{
    const int b = blockIdx.x * blockDim.x + threadIdx.x;
    if (b >= NB) return;

    float cur = uhT[b];
    float u0w = 0.f;
    #pragma unroll 4
    for (int i = 0; i < 255; i++) {
        float s, c; sincosf(thT[(size_t)i * NB + b], &s, &c);
        float nxt = uhT[(size_t)(i + 1) * NB + b];
        float wi = c * cur - s * nxt;
        urT[(size_t)i * NB + b] = wi;
        if (i == 0) u0w = wi;
        cur = s * cur + c * nxt;
    }
    {
        float s, c; sincosf(thT[(size_t)255 * NB + b], &s, &c);
        float w255 = c * cur - s * u0w;
        float w0   = s * cur + c * u0w;
        urT[(size_t)255 * NB + b] = w255;
        urT[b] = w0;
    }

    float dhr = 0.f, dht = 0.f, drt = 0.f, ssq = 0.f;
    const float uh0 = uhT[b], ut0 = utT[b];
    cur = urT[b];
    float w0sav = 0.f;
    #pragma unroll 4
    for (int i = 0; i < 255; i++) {
        float s, c; sincosf(thT[(size_t)(256 + i) * NB + b], &s, &c);
        float nxt = urT[(size_t)(i + 1) * NB + b];
        float wi = c * cur - s * nxt;
        cur = s * cur + c * nxt;
        if (i == 0) {
            w0sav = wi;
        } else {
            float uh = uhT[(size_t)i * NB + b];
            float ut = utT[(size_t)i * NB + b];
            ssq += wi * wi; dhr += wi * uh; drt += wi * ut; dht += uh * ut;
        }
    }
    float w255f, w0f;
    {
        float s, c; sincosf(thT[(size_t)511 * NB + b], &s, &c);
        w255f = c * cur - s * w0sav;
        w0f   = s * cur + c * w0sav;
    }
    {
        float uh255 = uhT[(size_t)255 * NB + b], ut255 = utT[(size_t)255 * NB + b];
        ssq += w255f * w255f + w0f * w0f;
        dhr += w255f * uh255 + w0f * uh0;
        drt += w255f * ut255 + w0f * ut0;
        dht += uh255 * ut255 + uh0 * ut0;
    }

    float nr = sqrtf(ssq);
    float inv_rot = 1.f / (nr + EPSF);
    float dhr_n = dhr * inv_rot;
    float dotc = fminf(fmaxf(dhr_n, -1.f + EPSF), 1.f - EPSF);
    float omega = acosf(dotc);
    float sin_om = sinf(omega);
    float sv = sim[b];
    float grho = 1.f / (1.f + expf(-(ga_rho[0] * sv + gb_rho[0])));
    float gphi = 1.f / (1.f + expf(-(ga_phi[0] * sv + gb_phi[0])));
    float ca, cb;
    if (omega > DELTAF) {
        float iso = 1.f / (sin_om + EPSF);
        ca = sinf((1.f - gphi) * omega) * iso;
        cb = sinf(gphi * omega) * iso;
    } else {
        ca = 1.f - gphi; cb = gphi;
    }
    float nrn = nr * inv_rot;
    float np2 = ca * ca + cb * cb * nrn * nrn + 2.f * ca * cb * dhr_n;
    float npv = sqrtf(fmaxf(np2, 0.f));
    float inv_np = 1.f / (npv + EPSF);
    float dpt = (ca * dht + cb * drt * inv_rot) * inv_np;

    float rho_h = fminf(softplusf(reh[b]), RHO_MAXF);
    float rho_p = fminf(fmaxf(rho_h + rrr[b] * grho, 0.f), RHO_MAXF);
    float rho_t = fminf(softplusf(ret[b]), RHO_MAXF);
    out[b] = -coshf(rho_p) * coshf(rho_t) + sinhf(rho_p) * sinhf(rho_t) * dpt;
}

// ---------------- launch --------------------------------------------------------------
extern "C" void kernel_launch(void* const* d_in, const int* in_sizes, int n_in,
                              void* d_out, int out_size)
{
    const float* ent  = (const float*)d_in[0];
    const float* rel  = (const float*)d_in[1];
    const float* lab  = (const float*)d_in[2];
    const float* sim  = (const float*)d_in[3];
    const float* Wv   = (const float*)d_in[4];
    const float* bv   = (const float*)d_in[5];
    const float* Wre  = (const float*)d_in[6];
    const float* bre  = (const float*)d_in[7];
    const float* Wrr  = (const float*)d_in[8];
    const float* brr  = (const float*)d_in[9];
    const float* Wt   = (const float*)d_in[10];
    const float* bt   = (const float*)d_in[11];
    const float* ga_rho = (const float*)d_in[12];
    const float* gb_rho = (const float*)d_in[13];
    const float* ga_phi = (const float*)d_in[14];
    const float* gb_phi = (const float*)d_in[15];
    const float* W1   = (const float*)d_in[16];
    const float* b1   = (const float*)d_in[17];
    const float* W2   = (const float*)d_in[18];
    const float* b2   = (const float*)d_in[19];
    float* out = (float*)d_out;

    float *H, *Eh, *Er, *Et, *Vh, *Vt, *TH, *thT, *uhT, *utT, *urT;
    float *reh, *rrr, *ret, *invh, *invt;
    cudaGetSymbolAddress((void**)&H,   g_H);
    cudaGetSymbolAddress((void**)&Eh,  g_Eh);
    cudaGetSymbolAddress((void**)&Er,  g_Er);
    cudaGetSymbolAddress((void**)&Et,  g_Et);
    cudaGetSymbolAddress((void**)&Vh,  g_Vh);
    cudaGetSymbolAddress((void**)&Vt,  g_Vt);
    cudaGetSymbolAddress((void**)&TH,  g_TH);
    cudaGetSymbolAddress((void**)&thT, g_thT);
    cudaGetSymbolAddress((void**)&uhT, g_uhT);
    cudaGetSymbolAddress((void**)&utT, g_utT);
    cudaGetSymbolAddress((void**)&urT, g_urT);
    cudaGetSymbolAddress((void**)&reh, g_reh);
    cudaGetSymbolAddress((void**)&rrr, g_rrr);
    cudaGetSymbolAddress((void**)&ret, g_ret);
    cudaGetSymbolAddress((void**)&invh, g_invh);
    cudaGetSymbolAddress((void**)&invt, g_invt);

    dim3 g4(4, NB / 128), g2(2, NB / 128), blk(256);

    // pre(x) = x + relu(x@W1^T + b1)@W2^T + b2 for the three embeddings
    sgemm_tf32<<<g4, blk>>>(ent, W1, b1, nullptr, H,  NB, HD, HD, 1);
    sgemm_tf32<<<g4, blk>>>(H,   W2, b2, ent,     Eh, NB, HD, HD, 2);
    sgemm_tf32<<<g4, blk>>>(rel, W1, b1, nullptr, H,  NB, HD, HD, 1);
    sgemm_tf32<<<g4, blk>>>(H,   W2, b2, rel,     Er, NB, HD, HD, 2);
    sgemm_tf32<<<g4, blk>>>(lab, W1, b1, nullptr, H,  NB, HD, HD, 1);
    sgemm_tf32<<<g4, blk>>>(H,   W2, b2, lab,     Et, NB, HD, HD, 2);

    // polar projections + theta logits
    sgemm_tf32<<<g2, blk>>>(Eh, Wv, bv, nullptr, Vh, NB, DV, HD, 0);
    sgemm_tf32<<<g2, blk>>>(Et, Wv, bv, nullptr, Vt, NB, DV, HD, 0);
    sgemm_tf32<<<g4, blk>>>(Er, Wt, bt, nullptr, TH, NB, NP, HD, 0);

    // scalar GEMVs (rho logits / delta_rho)
    gemv3<<<NB / 8, 256>>>(Eh, Er, Et, Wre, bre, Wrr, brr, reh, rrr, ret);

    // row norms + normalized transposes for coalesced rotation access
    rownorm<<<NB / 8, 256>>>(Vh, invh, DV);
    rownorm<<<NB / 8, 256>>>(Vt, invt, DV);
    transpose_op<<<dim3(NP / 32, NB / 32), dim3(32, 8)>>>(TH, thT, nullptr, NP, 0);
    transpose_op<<<dim3(DV / 32, NB / 32), dim3(32, 8)>>>(Vh, uhT, invh, DV, 1);
    transpose_op<<<dim3(DV / 32, NB / 32), dim3(32, 8)>>>(Vt, utT, invt, DV, 1);

    // fused Givens sweeps + slerp + hyperbolic score
    rot_score<<<NB / 256, 256>>>(uhT, utT, thT, urT, sim, reh, rrr, ret,
                                 ga_rho, gb_rho, ga_phi, gb_phi, out);
    (void)in_sizes; (void)n_in; (void)out_size;
}

// round 4
// speedup vs baseline: 4.7642x; 1.2351x over previous
#include <cuda_runtime.h>
#include <math.h>
#include <stdint.h>

#define NB 32768
#define HD 512
#define DV 256
#define NP 512
#define RHO_MAXF 9.0f
#define DELTAF 0.001f
#define EPSF 1e-8f
#define PIF 3.14159265358979f

// ---------------- scratch (__device__ globals: no allocations allowed) ----------------
__device__ float g_H [NB*HD];
__device__ float g_Eh[NB*HD];
__device__ float g_Er[NB*HD];
__device__ float g_Et[NB*HD];
__device__ float g_Vh[NB*DV];
__device__ float g_Vt[NB*DV];
__device__ float g_TH[NB*NP];
__device__ float g_thT[NP*NB];
__device__ float g_uhT[DV*NB];
__device__ float g_utT[DV*NB];
__device__ float g_urT[DV*NB];
__device__ float g_reh[NB];
__device__ float g_rrr[NB];
__device__ float g_ret[NB];
__device__ float g_invh[NB];
__device__ float g_invt[NB];

__device__ __forceinline__ float softplusf(float x) {
    return (x > 20.f) ? x : log1pf(expf(x));
}

__device__ __forceinline__ uint32_t f2tf32(float x) {
    uint32_t r;
    asm("cvt.rna.tf32.f32 %0, %1;" : "=r"(r) : "f"(x));
    return r;
}

// ---------------- TF32 tensor-core NT GEMM ------------------------------------------
// C[M,N] = A[M,K] * W[N,K]^T + bias (+relu | +residual)
// Block 128x128, 4 warps (2m x 2n), warp tile 64x64, KTILE=16 (2 k-steps of 8).
// Smem row stride = 20 words (16 + 4 pad) -> conflict-free fragment reads.
#define SMS 20

__global__ __launch_bounds__(128, 2)
void sgemm_tf32(const float* __restrict__ A, const float* __restrict__ Wm,
                const float* __restrict__ bias, const float* __restrict__ R,
                float* __restrict__ C, int M, int N, int K, int mode)
{
    __shared__ uint32_t As[2][128 * SMS];
    __shared__ uint32_t Bs[2][128 * SMS];

    const int tid  = threadIdx.x;
    const int wid  = tid >> 5;
    const int lane = tid & 31;
    const int g    = lane >> 2;     // group id 0..7
    const int tg   = lane & 3;      // thread-in-group 0..3
    const int m0   = blockIdx.y * 128;
    const int n0   = blockIdx.x * 128;
    const int moff = (wid & 1) * 64;
    const int noff = (wid >> 1) * 64;

    // global load mapping: 4 float4 per thread per tile per matrix (128 threads)
    // idx = tid + 128*p, p=0..3 ; row = idx>>2 (0..127) ; col4 = (idx&3)*4
    const int r0l = tid >> 2;          // 0..31
    const int c0l = (tid & 3) * 4;

    const float* Ag = A  + (size_t)(m0) * K;
    const float* Bg = Wm + (size_t)(n0) * K;

    float acc[4][8][4];
    #pragma unroll
    for (int mt = 0; mt < 4; mt++)
        #pragma unroll
        for (int nt = 0; nt < 8; nt++)
            #pragma unroll
            for (int q = 0; q < 4; q++) acc[mt][nt][q] = 0.f;

    // ---- load tile 0 ----
    {
        #pragma unroll
        for (int p = 0; p < 4; p++) {
            const int row = r0l + p * 32;
            float4 a4 = *(const float4*)&Ag[(size_t)row * K + c0l];
            float4 b4 = *(const float4*)&Bg[(size_t)row * K + c0l];
            uint32_t* as = &As[0][row * SMS + c0l];
            uint32_t* bs = &Bs[0][row * SMS + c0l];
            as[0] = f2tf32(a4.x); as[1] = f2tf32(a4.y); as[2] = f2tf32(a4.z); as[3] = f2tf32(a4.w);
            bs[0] = f2tf32(b4.x); bs[1] = f2tf32(b4.y); bs[2] = f2tf32(b4.z); bs[3] = f2tf32(b4.w);
        }
    }
    __syncthreads();

    const int kt = K >> 4;   // number of 16-wide K tiles
    int buf = 0;
    for (int t = 0; t < kt; ++t) {
        float4 na[4], nb[4];
        if (t + 1 < kt) {
            const int k0 = (t + 1) * 16;
            #pragma unroll
            for (int p = 0; p < 4; p++) {
                const int row = r0l + p * 32;
                na[p] = *(const float4*)&Ag[(size_t)row * K + k0 + c0l];
                nb[p] = *(const float4*)&Bg[(size_t)row * K + k0 + c0l];
            }
        }

        #pragma unroll
        for (int ks = 0; ks < 2; ++ks) {
            const int kb = ks * 8;
            uint32_t bf[8][2];
            #pragma unroll
            for (int nt = 0; nt < 8; nt++) {
                const int nr = noff + nt * 8 + g;
                bf[nt][0] = Bs[buf][nr * SMS + kb + tg];
                bf[nt][1] = Bs[buf][nr * SMS + kb + tg + 4];
            }
            #pragma unroll
            for (int mt = 0; mt < 4; mt++) {
                uint32_t af[4];
                const int r = moff + mt * 16 + g;
                af[0] = As[buf][r * SMS + kb + tg];
                af[1] = As[buf][(r + 8) * SMS + kb + tg];
                af[2] = As[buf][r * SMS + kb + tg + 4];
                af[3] = As[buf][(r + 8) * SMS + kb + tg + 4];
                #pragma unroll
                for (int nt = 0; nt < 8; nt++) {
                    asm volatile(
                        "mma.sync.aligned.m16n8k8.row.col.f32.tf32.tf32.f32 "
                        "{%0,%1,%2,%3}, {%4,%5,%6,%7}, {%8,%9}, {%0,%1,%2,%3};"
                        : "+f"(acc[mt][nt][0]), "+f"(acc[mt][nt][1]),
                          "+f"(acc[mt][nt][2]), "+f"(acc[mt][nt][3])
                        : "r"(af[0]), "r"(af[1]), "r"(af[2]), "r"(af[3]),
                          "r"(bf[nt][0]), "r"(bf[nt][1]));
                }
            }
        }

        if (t + 1 < kt) {
            const int nbuf = buf ^ 1;
            #pragma unroll
            for (int p = 0; p < 4; p++) {
                const int row = r0l + p * 32;
                uint32_t* as = &As[nbuf][row * SMS + c0l];
                uint32_t* bs = &Bs[nbuf][row * SMS + c0l];
                as[0] = f2tf32(na[p].x); as[1] = f2tf32(na[p].y); as[2] = f2tf32(na[p].z); as[3] = f2tf32(na[p].w);
                bs[0] = f2tf32(nb[p].x); bs[1] = f2tf32(nb[p].y); bs[2] = f2tf32(nb[p].z); bs[3] = f2tf32(nb[p].w);
            }
            __syncthreads();
            buf = nbuf;
        }
    }

    // ---- epilogue ----
    #pragma unroll
    for (int mt = 0; mt < 4; mt++) {
        #pragma unroll
        for (int nt = 0; nt < 8; nt++) {
            const int n = n0 + noff + nt * 8 + 2 * tg;
            const int ra = m0 + moff + mt * 16 + g;
            const int rb = ra + 8;
            float bx = bias[n], by = bias[n + 1];
            float2 v0 = make_float2(acc[mt][nt][0] + bx, acc[mt][nt][1] + by);
            float2 v1 = make_float2(acc[mt][nt][2] + bx, acc[mt][nt][3] + by);
            if (mode == 1) {
                v0.x = fmaxf(v0.x, 0.f); v0.y = fmaxf(v0.y, 0.f);
                v1.x = fmaxf(v1.x, 0.f); v1.y = fmaxf(v1.y, 0.f);
            } else if (mode == 2) {
                float2 r0v = *(const float2*)&R[(size_t)ra * N + n];
                float2 r1v = *(const float2*)&R[(size_t)rb * N + n];
                v0.x += r0v.x; v0.y += r0v.y;
                v1.x += r1v.x; v1.y += r1v.y;
            }
            *(float2*)&C[(size_t)ra * N + n] = v0;
            *(float2*)&C[(size_t)rb * N + n] = v1;
        }
    }
}

// ---------------- three N=1 GEMVs fused: re_h, rr_r, re_t -----------------------------
__device__ __forceinline__ float dot4f(float4 a, float4 b) {
    return a.x*b.x + a.y*b.y + a.z*b.z + a.w*b.w;
}

__global__ void gemv3(const float* __restrict__ Eh, const float* __restrict__ Er,
                      const float* __restrict__ Et,
                      const float* __restrict__ Wre, const float* __restrict__ bre,
                      const float* __restrict__ Wrr, const float* __restrict__ brr,
                      float* __restrict__ reh, float* __restrict__ rrr, float* __restrict__ ret)
{
    const int warp = (blockIdx.x * blockDim.x + threadIdx.x) >> 5;
    const int lane = threadIdx.x & 31;
    if (warp >= NB) return;
    const float* eh = Eh + (size_t)warp * HD;
    const float* er = Er + (size_t)warp * HD;
    const float* et = Et + (size_t)warp * HD;
    float s1 = 0.f, s2 = 0.f, s3 = 0.f;
    #pragma unroll
    for (int k = lane * 4; k < HD; k += 128) {
        float4 wre4 = *(const float4*)&Wre[k];
        float4 wrr4 = *(const float4*)&Wrr[k];
        s1 += dot4f(*(const float4*)&eh[k], wre4);
        s2 += dot4f(*(const float4*)&er[k], wrr4);
        s3 += dot4f(*(const float4*)&et[k], wre4);
    }
    #pragma unroll
    for (int o = 16; o > 0; o >>= 1) {
        s1 += __shfl_down_sync(0xffffffffu, s1, o);
        s2 += __shfl_down_sync(0xffffffffu, s2, o);
        s3 += __shfl_down_sync(0xffffffffu, s3, o);
    }
    if (lane == 0) {
        reh[warp] = s1 + bre[0];
        rrr[warp] = s2 + brr[0];
        ret[warp] = s3 + bre[0];
    }
}

// ---------------- row inverse-norm (warp per row) -------------------------------------
__global__ void rownorm(const float* __restrict__ V, float* __restrict__ inv, int W)
{
    const int warp = (blockIdx.x * blockDim.x + threadIdx.x) >> 5;
    const int lane = threadIdx.x & 31;
    if (warp >= NB) return;
    const float* v = V + (size_t)warp * W;
    float s = 0.f;
    for (int k = lane * 4; k < W; k += 128) {
        float4 a = *(const float4*)&v[k];
        s += a.x*a.x + a.y*a.y + a.z*a.z + a.w*a.w;
    }
    #pragma unroll
    for (int o = 16; o > 0; o >>= 1) s += __shfl_down_sync(0xffffffffu, s, o);
    if (lane == 0) inv[warp] = 1.f / (sqrtf(s) + EPSF);
}

// ---------------- transpose (+ optional pi*tanh or per-row scale) ---------------------
// mode 0: out[c, b] = pi * tanhf(in[b, c]);  mode 1: out[c, b] = in[b, c] * inv[b]
__global__ void transpose_op(const float* __restrict__ in, float* __restrict__ out,
                             const float* __restrict__ inv, int N, int mode)
{
    __shared__ float tile[32][33];
    const int tx = threadIdx.x, ty = threadIdx.y;
    const int x = blockIdx.x * 32 + tx;
    const int y0 = blockIdx.y * 32;
    #pragma unroll
    for (int j = ty; j < 32; j += 8)
        tile[j][tx] = in[(size_t)(y0 + j) * N + x];
    __syncthreads();
    const int b = y0 + tx;
    const int c0 = blockIdx.x * 32;
    float scale = (mode == 1) ? inv[b] : 1.f;
    #pragma unroll
    for (int j = ty; j < 32; j += 8) {
        float v = tile[tx][j];
        if (mode == 0) v = PIF * tanhf(v);
        else v *= scale;
        out[(size_t)(c0 + j) * NB + b] = v;
    }
}

// ---------------- fused rotation + slerp + score --------------------------------------
__global__ void rot_score(
    const float* __restrict__ uhT, const float* __restrict__ utT,
    const float* __restrict__ thT, float* __restrict__ urT,
    const float* __restrict__ sim,
    const float* __restrict__ reh, const float* __restrict__ rrr, const float* __restrict__ ret,
    const float* __restrict__ ga_rho, const float* __restrict__ gb_rho,
    const float* __restrict__ ga_phi, const float* __restrict__ gb_phi,
    float* __restrict__ out)
{
    const int b = blockIdx.x * blockDim.x + threadIdx.x;
    if (b >= NB) return;

    float cur = uhT[b];
    float u0w = 0.f;
    #pragma unroll 4
    for (int i = 0; i < 255; i++) {
        float s, c; __sincosf(thT[(size_t)i * NB + b], &s, &c);
        float nxt = uhT[(size_t)(i + 1) * NB + b];
        float wi = c * cur - s * nxt;
        urT[(size_t)i * NB + b] = wi;
        if (i == 0) u0w = wi;
        cur = s * cur + c * nxt;
    }
    {
        float s, c; __sincosf(thT[(size_t)255 * NB + b], &s, &c);
        float w255 = c * cur - s * u0w;
        float w0   = s * cur + c * u0w;
        urT[(size_t)255 * NB + b] = w255;
        urT[b] = w0;
    }

    float dhr = 0.f, dht = 0.f, drt = 0.f, ssq = 0.f;
    const float uh0 = uhT[b], ut0 = utT[b];
    cur = urT[b];
    float w0sav = 0.f;
    #pragma unroll 4
    for (int i = 0; i < 255; i++) {
        float s, c; __sincosf(thT[(size_t)(256 + i) * NB + b], &s, &c);
        float nxt = urT[(size_t)(i + 1) * NB + b];
        float wi = c * cur - s * nxt;
        cur = s * cur + c * nxt;
        if (i == 0) {
            w0sav = wi;
        } else {
            float uh = uhT[(size_t)i * NB + b];
            float ut = utT[(size_t)i * NB + b];
            ssq += wi * wi; dhr += wi * uh; drt += wi * ut; dht += uh * ut;
        }
    }
    float w255f, w0f;
    {
        float s, c; __sincosf(thT[(size_t)511 * NB + b], &s, &c);
        w255f = c * cur - s * w0sav;
        w0f   = s * cur + c * w0sav;
    }
    {
        float uh255 = uhT[(size_t)255 * NB + b], ut255 = utT[(size_t)255 * NB + b];
        ssq += w255f * w255f + w0f * w0f;
        dhr += w255f * uh255 + w0f * uh0;
        drt += w255f * ut255 + w0f * ut0;
        dht += uh255 * ut255 + uh0 * ut0;
    }

    float nr = sqrtf(ssq);
    float inv_rot = 1.f / (nr + EPSF);
    float dhr_n = dhr * inv_rot;
    float dotc = fminf(fmaxf(dhr_n, -1.f + EPSF), 1.f - EPSF);
    float omega = acosf(dotc);
    float sin_om = sinf(omega);
    float sv = sim[b];
    float grho = 1.f / (1.f + expf(-(ga_rho[0] * sv + gb_rho[0])));
    float gphi = 1.f / (1.f + expf(-(ga_phi[0] * sv + gb_phi[0])));
    float ca, cb;
    if (omega > DELTAF) {
        float iso = 1.f / (sin_om + EPSF);
        ca = sinf((1.f - gphi) * omega) * iso;
        cb = sinf(gphi * omega) * iso;
    } else {
        ca = 1.f - gphi; cb = gphi;
    }
    float nrn = nr * inv_rot;
    float np2 = ca * ca + cb * cb * nrn * nrn + 2.f * ca * cb * dhr_n;
    float npv = sqrtf(fmaxf(np2, 0.f));
    float inv_np = 1.f / (npv + EPSF);
    float dpt = (ca * dht + cb * drt * inv_rot) * inv_np;

    float rho_h = fminf(softplusf(reh[b]), RHO_MAXF);
    float rho_p = fminf(fmaxf(rho_h + rrr[b] * grho, 0.f), RHO_MAXF);
    float rho_t = fminf(softplusf(ret[b]), RHO_MAXF);
    out[b] = -coshf(rho_p) * coshf(rho_t) + sinhf(rho_p) * sinhf(rho_t) * dpt;
}

// ---------------- launch --------------------------------------------------------------
extern "C" void kernel_launch(void* const* d_in, const int* in_sizes, int n_in,
                              void* d_out, int out_size)
{
    const float* ent  = (const float*)d_in[0];
    const float* rel  = (const float*)d_in[1];
    const float* lab  = (const float*)d_in[2];
    const float* sim  = (const float*)d_in[3];
    const float* Wv   = (const float*)d_in[4];
    const float* bv   = (const float*)d_in[5];
    const float* Wre  = (const float*)d_in[6];
    const float* bre  = (const float*)d_in[7];
    const float* Wrr  = (const float*)d_in[8];
    const float* brr  = (const float*)d_in[9];
    const float* Wt   = (const float*)d_in[10];
    const float* bt   = (const float*)d_in[11];
    const float* ga_rho = (const float*)d_in[12];
    const float* gb_rho = (const float*)d_in[13];
    const float* ga_phi = (const float*)d_in[14];
    const float* gb_phi = (const float*)d_in[15];
    const float* W1   = (const float*)d_in[16];
    const float* b1   = (const float*)d_in[17];
    const float* W2   = (const float*)d_in[18];
    const float* b2   = (const float*)d_in[19];
    float* out = (float*)d_out;

    float *H, *Eh, *Er, *Et, *Vh, *Vt, *TH, *thT, *uhT, *utT, *urT;
    float *reh, *rrr, *ret, *invh, *invt;
    cudaGetSymbolAddress((void**)&H,   g_H);
    cudaGetSymbolAddress((void**)&Eh,  g_Eh);
    cudaGetSymbolAddress((void**)&Er,  g_Er);
    cudaGetSymbolAddress((void**)&Et,  g_Et);
    cudaGetSymbolAddress((void**)&Vh,  g_Vh);
    cudaGetSymbolAddress((void**)&Vt,  g_Vt);
    cudaGetSymbolAddress((void**)&TH,  g_TH);
    cudaGetSymbolAddress((void**)&thT, g_thT);
    cudaGetSymbolAddress((void**)&uhT, g_uhT);
    cudaGetSymbolAddress((void**)&utT, g_utT);
    cudaGetSymbolAddress((void**)&urT, g_urT);
    cudaGetSymbolAddress((void**)&reh, g_reh);
    cudaGetSymbolAddress((void**)&rrr, g_rrr);
    cudaGetSymbolAddress((void**)&ret, g_ret);
    cudaGetSymbolAddress((void**)&invh, g_invh);
    cudaGetSymbolAddress((void**)&invt, g_invt);

    dim3 g4(4, NB / 128), g2(2, NB / 128), blk(128);

    // pre(x) = x + relu(x@W1^T + b1)@W2^T + b2 for the three embeddings
    sgemm_tf32<<<g4, blk>>>(ent, W1, b1, nullptr, H,  NB, HD, HD, 1);
    sgemm_tf32<<<g4, blk>>>(H,   W2, b2, ent,     Eh, NB, HD, HD, 2);
    sgemm_tf32<<<g4, blk>>>(rel, W1, b1, nullptr, H,  NB, HD, HD, 1);
    sgemm_tf32<<<g4, blk>>>(H,   W2, b2, rel,     Er, NB, HD, HD, 2);
    sgemm_tf32<<<g4, blk>>>(lab, W1, b1, nullptr, H,  NB, HD, HD, 1);
    sgemm_tf32<<<g4, blk>>>(H,   W2, b2, lab,     Et, NB, HD, HD, 2);

    // polar projections + theta logits
    sgemm_tf32<<<g2, blk>>>(Eh, Wv, bv, nullptr, Vh, NB, DV, HD, 0);
    sgemm_tf32<<<g2, blk>>>(Et, Wv, bv, nullptr, Vt, NB, DV, HD, 0);
    sgemm_tf32<<<g4, blk>>>(Er, Wt, bt, nullptr, TH, NB, NP, HD, 0);

    // scalar GEMVs (rho logits / delta_rho)
    gemv3<<<NB / 8, 256>>>(Eh, Er, Et, Wre, bre, Wrr, brr, reh, rrr, ret);

    // row norms + normalized transposes for coalesced rotation access
    rownorm<<<NB / 8, 256>>>(Vh, invh, DV);
    rownorm<<<NB / 8, 256>>>(Vt, invt, DV);
    transpose_op<<<dim3(NP / 32, NB / 32), dim3(32, 8)>>>(TH, thT, nullptr, NP, 0);
    transpose_op<<<dim3(DV / 32, NB / 32), dim3(32, 8)>>>(Vh, uhT, invh, DV, 1);
    transpose_op<<<dim3(DV / 32, NB / 32), dim3(32, 8)>>>(Vt, utT, invt, DV, 1);

    // fused Givens sweeps + slerp + hyperbolic score
    rot_score<<<NB / 256, 256>>>(uhT, utT, thT, urT, sim, reh, rrr, ret,
                                 ga_rho, gb_rho, ga_phi, gb_phi, out);
    (void)in_sizes; (void)n_in; (void)out_size;
}